// round 13
// baseline (speedup 1.0000x reference)
#include <cuda_runtime.h>
#include <cuda_fp16.h>
#include <cstdint>

#define DI __device__ __forceinline__

// ---------------- scratch (device globals; no allocation allowed) ----------
__device__ float  g_t1[192 * 192];
__device__ __half g_t2h[6144 * 384];           // t2 fp16, row-major [6144][384]
__device__ __half g_c3h[384 * 384];            // core3 fp16 pairs [kp][n][2]
__device__ float  g_t3[192 * 768 * 16];
__device__ __half g_Mh[768 * 3072];            // [kp=k/2][n][2] fp16 pairs
__device__ __half g_Xh[32768UL * 768];         // X fp16, plain [row][k]

// ---------------- helpers ---------------------------------------------------
DI uint32_t smem_u32(const void* p) {
    uint32_t a;
    asm("{ .reg .u64 t; cvta.to.shared.u64 t, %1; cvt.u32.u64 %0, t; }" : "=r"(a) : "l"(p));
    return a;
}
DI void mma_f16(float c[4], const uint32_t a[4], const uint32_t b[2]) {
    asm("mma.sync.aligned.m16n8k16.row.col.f32.f16.f16.f32 "
        "{%0,%1,%2,%3}, {%4,%5,%6,%7}, {%8,%9}, {%0,%1,%2,%3};"
        : "+f"(c[0]), "+f"(c[1]), "+f"(c[2]), "+f"(c[3])
        : "r"(a[0]), "r"(a[1]), "r"(a[2]), "r"(a[3]),
          "r"(b[0]), "r"(b[1]));
}
DI void ldsm_x4(uint32_t r[4], uint32_t addr) {
    asm volatile("ldmatrix.sync.aligned.m8n8.x4.shared.b16 {%0,%1,%2,%3}, [%4];"
        : "=r"(r[0]), "=r"(r[1]), "=r"(r[2]), "=r"(r[3]) : "r"(addr));
}
#define CP16(d, s)  asm volatile("cp.async.cg.shared.global [%0], [%1], 16;" :: "r"(d), "l"(s) : "memory")
#define CP_COMMIT() asm volatile("cp.async.commit_group;" ::: "memory")
#define CP_WAIT1()  asm volatile("cp.async.wait_group 1;" ::: "memory")

// ---------------- X prepass: fp32 -> fp16 ------------------------------------
__global__ void k_pre(const float* __restrict__ X) {
    size_t i = (size_t)blockIdx.x * blockDim.x + threadIdx.x;
    float4 v = *(const float4*)(X + i * 4);
    __half2 h0 = __floats2half2_rn(v.x, v.y);
    __half2 h1 = __floats2half2_rn(v.z, v.w);
    *(uint2*)(g_Xh + i * 4) = make_uint2(*(uint32_t*)&h0, *(uint32_t*)&h1);
}

// ---------------- step 1: t1 = core0 x core1 [192x192] ----------------------
__global__ void k_t1(const float* __restrict__ c0, const float* __restrict__ c1) {
    int idx = blockIdx.x * blockDim.x + threadIdx.x;
    if (idx >= 192 * 192) return;
    int p = idx / 192, q = idx % 192;
    int Ii = p >> 4, Oo = p & 15;
    int I = Ii >> 2, i = Ii & 3, O = Oo >> 2, o = Oo & 3;
    float acc = 0.f;
#pragma unroll
    for (int r = 0; r < 12; ++r)
        acc += c0[(I * 4 + O) * 12 + r] * c1[((r * 4 + i) * 4 + o) * 192 + q];
    g_t1[idx] = acc;
}

// ---------------- core3 -> fp16 pair layout ----------------------------------
__global__ void k_c3h(const float* __restrict__ c3) {
    int idx = blockIdx.x * 256 + threadIdx.x;    // < 147456
    int k = idx / 384, n = idx % 384;
    g_c3h[((size_t)(k >> 1) * 384 + n) * 2 + (k & 1)] = __float2half_rn(c3[idx]);
}

// ---------------- mid0 GEMM (fp32 SIMT), fused t2 store as fp16 -------------
__global__ void gemm_mid0(const float* __restrict__ B) {
    const float* __restrict__ A = g_t1;
    __shared__ float As[16][68];
    __shared__ float Bs[16][64];
    int tid = threadIdx.x;
    int bm = blockIdx.y * 64, bn = blockIdx.x * 64;
    int row = (tid / 16) * 4, col = (tid % 16) * 4;
    float acc[4][4] = {};
    int arow = tid >> 2, ac = (tid & 3) * 4;
    int brow = tid >> 4, bc = (tid & 15) * 4;
    const int N = 12288, K = 192;
    for (int kt = 0; kt < K; kt += 16) {
        float4 av = *(const float4*)&A[(size_t)(bm + arow) * K + kt + ac];
        float4 bv = *(const float4*)&B[(size_t)(kt + brow) * N + bn + bc];
        __syncthreads();
        As[ac + 0][arow] = av.x; As[ac + 1][arow] = av.y;
        As[ac + 2][arow] = av.z; As[ac + 3][arow] = av.w;
        *(float4*)&Bs[brow][bc] = bv;
        __syncthreads();
#pragma unroll
        for (int kk = 0; kk < 16; ++kk) {
            float4 a = *(const float4*)&As[kk][row];
            float4 b = *(const float4*)&Bs[kk][col];
            float aa[4] = {a.x, a.y, a.z, a.w};
            float bb[4] = {b.x, b.y, b.z, b.w};
#pragma unroll
            for (int ii = 0; ii < 4; ++ii)
#pragma unroll
                for (int jj = 0; jj < 4; ++jj)
                    acc[ii][jj] += aa[ii] * bb[jj];
        }
    }
    int io = bn / 384, q0 = bn - io * 384;
    int i = io >> 3, o = io & 7;
#pragma unroll
    for (int ii = 0; ii < 4; ++ii) {
        int p = bm + row + ii;
        int Ii = p >> 4, Oo = p & 15;
        size_t base = ((size_t)((Ii * 4 + i) * 128 + Oo * 8 + o)) * 384 + q0 + col;
#pragma unroll
        for (int jj = 0; jj < 4; ++jj)
            g_t2h[base + jj] = __float2half_rn(acc[ii][jj]);
    }
}

// ---------------- mid1 GEMM fp16 mma: t3 = t2h x c3h, fused t3 layout -------
static constexpr int M1_A_ROW = 144;
static constexpr int M1_A_STG = 128 * M1_A_ROW;
static constexpr int M1_B_REG = 528;
static constexpr int M1_B_STG = 32 * M1_B_REG;
static constexpr int M1_STG   = M1_A_STG + M1_B_STG;
static constexpr int M1_SMEM  = 3 * M1_STG;

__global__ __launch_bounds__(256, 1)
void k_mid1h() {
    extern __shared__ char smem[];
    uint32_t sb = smem_u32(smem);
    int tid  = threadIdx.x;
    int warp = tid >> 5, lane = tid & 31;
    int wm = warp >> 2, wn = warp & 3;
    int g  = lane >> 2, tg = lane & 3;
    int bn = blockIdx.x * 128;
    int row0 = blockIdx.y * 128;

    float c[4][4][4] = {};

    int aRow = tid >> 1, aHalf = tid & 1;
    const __half* aSrc = g_t2h + (size_t)(row0 + aRow) * 384 + aHalf * 32;
    uint32_t aD0 = (uint32_t)(aRow * M1_A_ROW + aHalf * 64);
    const __half* bSrc = g_c3h + (size_t)bn * 2;

    uint32_t aLane = (uint32_t)((wm * 64 + (lane & 15)) * M1_A_ROW + (lane >> 4) * 16);

#pragma unroll
    for (int t = 0; t < 2; ++t) {
        uint32_t base = sb + t * M1_STG;
#pragma unroll
        for (int j = 0; j < 4; ++j)
            CP16(base + aD0 + j * 16, aSrc + t * 64 + j * 8);
#pragma unroll
        for (int i = 0; i < 4; ++i) {
            int q = tid + i * 256, r = q >> 5, n4 = (q & 31) * 4;
            CP16(base + M1_A_STG + (uint32_t)(r * M1_B_REG + n4 * 4),
                 bSrc + ((size_t)(t * 32 + r) * 384 + n4) * 2);
        }
        CP_COMMIT();
    }

    int s = 0;
    for (int t = 0; t < 6; ++t) {
        CP_WAIT1();
        __syncthreads();
        if (t + 2 < 6) {
            int tn = t + 2;
            int sn = s + 2; if (sn >= 3) sn -= 3;
            uint32_t base = sb + sn * M1_STG;
#pragma unroll
            for (int j = 0; j < 4; ++j)
                CP16(base + aD0 + j * 16, aSrc + tn * 64 + j * 8);
#pragma unroll
            for (int i = 0; i < 4; ++i) {
                int q = tid + i * 256, r = q >> 5, n4 = (q & 31) * 4;
                CP16(base + M1_A_STG + (uint32_t)(r * M1_B_REG + n4 * 4),
                     bSrc + ((size_t)(tn * 32 + r) * 384 + n4) * 2);
            }
        }
        CP_COMMIT();

        uint32_t abase = sb + s * M1_STG + aLane;
        const char* B = smem + s * M1_STG + M1_A_STG;

        uint32_t af[2][4][4], bf[2][4][2];
#pragma unroll
        for (int mf = 0; mf < 4; ++mf)
            ldsm_x4(af[0][mf], abase + mf * (16 * M1_A_ROW));
#pragma unroll
        for (int nf = 0; nf < 4; ++nf) {
            int n = wn * 32 + nf * 8 + g;
            bf[0][nf][0] = *(const uint32_t*)(B + tg * M1_B_REG + n * 4);
            bf[0][nf][1] = *(const uint32_t*)(B + (4 + tg) * M1_B_REG + n * 4);
        }
#pragma unroll
        for (int kg = 0; kg < 4; ++kg) {
            int cur = kg & 1, nxt = cur ^ 1;
            if (kg < 3) {
#pragma unroll
                for (int mf = 0; mf < 4; ++mf)
                    ldsm_x4(af[nxt][mf], abase + mf * (16 * M1_A_ROW) + (kg + 1) * 32);
#pragma unroll
                for (int nf = 0; nf < 4; ++nf) {
                    int n = wn * 32 + nf * 8 + g;
                    const char* br = B + (kg + 1) * 8 * M1_B_REG;
                    bf[nxt][nf][0] = *(const uint32_t*)(br + tg * M1_B_REG + n * 4);
                    bf[nxt][nf][1] = *(const uint32_t*)(br + (4 + tg) * M1_B_REG + n * 4);
                }
            }
#pragma unroll
            for (int mf = 0; mf < 4; ++mf)
#pragma unroll
                for (int nf = 0; nf < 4; ++nf)
                    mma_f16(c[mf][nf], af[cur][mf], bf[cur][nf]);
        }
        ++s; if (s == 3) s = 0;
    }

#pragma unroll
    for (int nf = 0; nf < 4; ++nf) {
#pragma unroll
        for (int e2 = 0; e2 < 2; ++e2) {
            int e = bn + wn * 32 + nf * 8 + tg * 2 + e2;
            int gg = e >> 4, q = e & 15;
            int i3 = gg / 6, o3 = gg - 6 * i3;
#pragma unroll
            for (int mf = 0; mf < 4; ++mf) {
#pragma unroll
                for (int r2 = 0; r2 < 2; ++r2) {
                    int r = row0 + wm * 64 + mf * 16 + g + r2 * 8;
                    int Ii2 = r >> 7, Oo2 = r & 127;
                    g_t3[((size_t)((Ii2 * 4 + i3) * 768 + Oo2 * 6 + o3)) * 16 + q]
                        = c[mf][nf][r2 * 2 + e2];
                }
            }
        }
    }
}

// step 4: build M as fp16 pairs g_Mh[(kp*3072 + n)*2 + (k&1)]
__global__ void k_t4(const float* __restrict__ c4) {
    __shared__ float Bs[256];
    int tid = threadIdx.x;
    Bs[tid] = c4[tid];
    __syncthreads();
    int p = blockIdx.x * 256 + tid;
    float a[16];
#pragma unroll
    for (int j = 0; j < 4; ++j) {
        float4 v = *(const float4*)&g_t3[(size_t)p * 16 + j * 4];
        a[j * 4 + 0] = v.x; a[j * 4 + 1] = v.y; a[j * 4 + 2] = v.z; a[j * 4 + 3] = v.w;
    }
    int Ii3 = p / 768, Oo3 = p % 768;
#pragma unroll
    for (int nn = 0; nn < 16; ++nn) {
        float acc = 0.f;
#pragma unroll
        for (int q = 0; q < 16; ++q) acc += a[q] * Bs[q * 16 + nn];
        int i4 = nn >> 2, o4 = nn & 3;
        int k = Ii3 * 4 + i4, n = Oo3 * 4 + o4;
        g_Mh[((size_t)(k >> 1) * 3072 + n) * 2 + (k & 1)] = __float2half_rn(acc);
    }
}

// ---------------- main GEMM: Y = X * M + bias, fp16 m16n8k16 ----------------
// BM=128, BN=128, BK=64; 128 threads, 4 warps (2x2), warp tile 64x64.
// OCCUPANCY 2 (decoupled CTAs) + R10 byte economics (64x64 warp tiles).
// Regs ~212/thread fits 256-reg cap at 128thr x occ2.
static constexpr int A_ROW_B  = 144;
static constexpr int A_STAGE  = 128 * A_ROW_B;        // 18432
static constexpr int B_REG_B  = 544;                  // 136w ≡ 8 mod 32
static constexpr int B_STAGE  = 32 * B_REG_B;         // 17408
static constexpr int STAGE    = A_STAGE + B_STAGE;    // 35840
static constexpr int SMEM_MAIN = 3 * STAGE;           // 107520

__global__ __launch_bounds__(128, 2)
void k_main(const float* __restrict__ bias, float* __restrict__ Y) {
    extern __shared__ char smem[];
    uint32_t sb = smem_u32(smem);

    int tid  = threadIdx.x;
    int warp = tid >> 5, lane = tid & 31;
    int wm = warp >> 1, wn = warp & 1;          // 2 x 2 warp grid
    int g  = lane >> 2, tg = lane & 3;

    int col0 = blockIdx.x * 128;
    int row0 = blockIdx.y * 128;

    float c[4][8][4] = {};

    // cp.async mappings (128 threads)
    // A: 1024 chunks/tile; thread: row=tid, 8 chunks along k
    const __half* aSrc = g_Xh + (size_t)(row0 + tid) * 768;
    uint32_t aD0 = (uint32_t)(tid * A_ROW_B);
    // B: 1024 chunks/tile; thread does 8: q = tid + i*128
    const __half* bSrc = g_Mh + (size_t)col0 * 2;

    uint32_t aLane = (uint32_t)((wm * 64 + (lane & 15)) * A_ROW_B + (lane >> 4) * 16);

#pragma unroll
    for (int t = 0; t < 2; ++t) {
        uint32_t base = sb + t * STAGE;
#pragma unroll
        for (int j = 0; j < 8; ++j)
            CP16(base + aD0 + j * 16, aSrc + t * 64 + j * 8);
#pragma unroll
        for (int i = 0; i < 8; ++i) {
            int q = tid + i * 128, r = q >> 5, n4 = (q & 31) * 4;
            CP16(base + A_STAGE + (uint32_t)(r * B_REG_B + n4 * 4),
                 bSrc + ((size_t)(t * 32 + r) * 3072 + n4) * 2);
        }
        CP_COMMIT();
    }

    int s = 0;
    for (int t = 0; t < 12; ++t) {
        CP_WAIT1();
        __syncthreads();

        if (t + 2 < 12) {
            int tn = t + 2;
            int sn = s + 2; if (sn >= 3) sn -= 3;
            uint32_t base = sb + sn * STAGE;
#pragma unroll
            for (int j = 0; j < 8; ++j)
                CP16(base + aD0 + j * 16, aSrc + tn * 64 + j * 8);
#pragma unroll
            for (int i = 0; i < 8; ++i) {
                int q = tid + i * 128, r = q >> 5, n4 = (q & 31) * 4;
                CP16(base + A_STAGE + (uint32_t)(r * B_REG_B + n4 * 4),
                     bSrc + ((size_t)(tn * 32 + r) * 3072 + n4) * 2);
            }
        }
        CP_COMMIT();

        uint32_t abase = sb + s * STAGE + aLane;
        const char* B = smem + s * STAGE + A_STAGE;

        uint32_t af[2][4][4], bf[2][8][2];
#pragma unroll
        for (int mf = 0; mf < 4; ++mf)
            ldsm_x4(af[0][mf], abase + mf * (16 * A_ROW_B));
#pragma unroll
        for (int nf = 0; nf < 8; ++nf) {
            int n = wn * 64 + nf * 8 + g;
            bf[0][nf][0] = *(const uint32_t*)(B + tg * B_REG_B + n * 4);
            bf[0][nf][1] = *(const uint32_t*)(B + (4 + tg) * B_REG_B + n * 4);
        }

#pragma unroll
        for (int kg = 0; kg < 4; ++kg) {
            int cur = kg & 1, nxt = cur ^ 1;
            if (kg < 3) {
#pragma unroll
                for (int mf = 0; mf < 4; ++mf)
                    ldsm_x4(af[nxt][mf], abase + mf * (16 * A_ROW_B) + (kg + 1) * 32);
#pragma unroll
                for (int nf = 0; nf < 8; ++nf) {
                    int n = wn * 64 + nf * 8 + g;
                    const char* br = B + (kg + 1) * 8 * B_REG_B;
                    bf[nxt][nf][0] = *(const uint32_t*)(br + tg * B_REG_B + n * 4);
                    bf[nxt][nf][1] = *(const uint32_t*)(br + (4 + tg) * B_REG_B + n * 4);
                }
            }
#pragma unroll
            for (int mf = 0; mf < 4; ++mf)
#pragma unroll
                for (int nf = 0; nf < 8; ++nf)
                    mma_f16(c[mf][nf], af[cur][mf], bf[cur][nf]);
        }
        ++s; if (s == 3) s = 0;
    }

    // epilogue: add bias, store
#pragma unroll
    for (int nf = 0; nf < 8; ++nf) {
        int cc = col0 + wn * 64 + nf * 8 + tg * 2;
        float b0 = bias[cc], b1 = bias[cc + 1];
#pragma unroll
        for (int mf = 0; mf < 4; ++mf) {
            int r = row0 + wm * 64 + mf * 16 + g;
            float2 v0 = make_float2(c[mf][nf][0] + b0, c[mf][nf][1] + b1);
            float2 v1 = make_float2(c[mf][nf][2] + b0, c[mf][nf][3] + b1);
            *(float2*)&Y[(size_t)r * 3072 + cc]       = v0;
            *(float2*)&Y[(size_t)(r + 8) * 3072 + cc] = v1;
        }
    }
}

// ---------------- launch -----------------------------------------------------
extern "C" void kernel_launch(void* const* d_in, const int* in_sizes, int n_in,
                              void* d_out, int out_size) {
    const float* x    = (const float*)d_in[0];
    const float* c0   = (const float*)d_in[1];
    const float* c1   = (const float*)d_in[2];
    const float* c2   = (const float*)d_in[3];
    const float* c3   = (const float*)d_in[4];
    const float* c4   = (const float*)d_in[5];
    const float* bias = (const float*)d_in[6];
    float* y = (float*)d_out;

    k_pre<<<(32768UL * 768 / 4) / 256, 256>>>(x);
    k_t1<<<144, 256>>>(c0, c1);
    k_c3h<<<147456 / 256, 256>>>(c3);
    {
        dim3 grid(12288 / 64, 192 / 64);
        gemm_mid0<<<grid, 256>>>(c2);
    }
    cudaFuncSetAttribute(k_mid1h, cudaFuncAttributeMaxDynamicSharedMemorySize, M1_SMEM);
    {
        dim3 grid(384 / 128, 6144 / 128);
        k_mid1h<<<grid, 256, M1_SMEM>>>();
    }
    k_t4<<<147456 / 256, 256>>>(c4);

    cudaFuncSetAttribute(k_main, cudaFuncAttributeMaxDynamicSharedMemorySize, SMEM_MAIN);
    {
        dim3 grid(3072 / 128, 32768 / 128);
        k_main<<<grid, 128, SMEM_MAIN>>>(bias, y);
    }
}

// round 14
// speedup vs baseline: 1.1391x; 1.1391x over previous
#include <cuda_runtime.h>
#include <cuda_fp16.h>
#include <cstdint>

#define DI __device__ __forceinline__

// ---------------- scratch (device globals; no allocation allowed) ----------
__device__ __half g_t1h[192 * 192];            // t1 fp16 row-major [192][192]
__device__ __half g_c2h[192 * 12288];          // core2 fp16 pairs [kp][n][2]
__device__ __half g_t2h[6144 * 384];           // t2 fp16, row-major [6144][384]
__device__ __half g_c3h[384 * 384];            // core3 fp16 pairs [kp][n][2]
__device__ float  g_t3[192 * 768 * 16];
__device__ __half g_Mh[768 * 3072];            // [kp=k/2][n][2] fp16 pairs
__device__ __half g_Xh[32768UL * 768];         // X fp16, plain [row][k]

// ---------------- helpers ---------------------------------------------------
DI uint32_t smem_u32(const void* p) {
    uint32_t a;
    asm("{ .reg .u64 t; cvta.to.shared.u64 t, %1; cvt.u32.u64 %0, t; }" : "=r"(a) : "l"(p));
    return a;
}
DI void mma_f16(float c[4], const uint32_t a[4], const uint32_t b[2]) {
    asm("mma.sync.aligned.m16n8k16.row.col.f32.f16.f16.f32 "
        "{%0,%1,%2,%3}, {%4,%5,%6,%7}, {%8,%9}, {%0,%1,%2,%3};"
        : "+f"(c[0]), "+f"(c[1]), "+f"(c[2]), "+f"(c[3])
        : "r"(a[0]), "r"(a[1]), "r"(a[2]), "r"(a[3]),
          "r"(b[0]), "r"(b[1]));
}
DI void ldsm_x4(uint32_t r[4], uint32_t addr) {
    asm volatile("ldmatrix.sync.aligned.m8n8.x4.shared.b16 {%0,%1,%2,%3}, [%4];"
        : "=r"(r[0]), "=r"(r[1]), "=r"(r[2]), "=r"(r[3]) : "r"(addr));
}
#define CP16(d, s)  asm volatile("cp.async.cg.shared.global [%0], [%1], 16;" :: "r"(d), "l"(s) : "memory")
#define CP_COMMIT() asm volatile("cp.async.commit_group;" ::: "memory")
#define CP_WAIT1()  asm volatile("cp.async.wait_group 1;" ::: "memory")

// ---------------- X prepass: fp32 -> fp16 ------------------------------------
__global__ void k_pre(const float* __restrict__ X) {
    size_t i = (size_t)blockIdx.x * blockDim.x + threadIdx.x;
    float4 v = *(const float4*)(X + i * 4);
    __half2 h0 = __floats2half2_rn(v.x, v.y);
    __half2 h1 = __floats2half2_rn(v.z, v.w);
    *(uint2*)(g_Xh + i * 4) = make_uint2(*(uint32_t*)&h0, *(uint32_t*)&h1);
}

// ---------------- step 1: t1 = core0 x core1 [192x192], fp16 out -------------
__global__ void k_t1(const float* __restrict__ c0, const float* __restrict__ c1) {
    int idx = blockIdx.x * blockDim.x + threadIdx.x;
    if (idx >= 192 * 192) return;
    int p = idx / 192, q = idx % 192;
    int Ii = p >> 4, Oo = p & 15;
    int I = Ii >> 2, i = Ii & 3, O = Oo >> 2, o = Oo & 3;
    float acc = 0.f;
#pragma unroll
    for (int r = 0; r < 12; ++r)
        acc += c0[(I * 4 + O) * 12 + r] * c1[((r * 4 + i) * 4 + o) * 192 + q];
    g_t1h[idx] = __float2half_rn(acc);
}

// ---------------- core2 -> fp16 pair layout [kp][n][2] ------------------------
__global__ void k_c2h(const float* __restrict__ c2) {
    int idx = blockIdx.x * 256 + threadIdx.x;    // < 2359296
    int k = idx / 12288, n = idx % 12288;
    g_c2h[((size_t)(k >> 1) * 12288 + n) * 2 + (k & 1)] = __float2half_rn(c2[idx]);
}

// ---------------- core3 -> fp16 pair layout ----------------------------------
__global__ void k_c3h(const float* __restrict__ c3) {
    int idx = blockIdx.x * 256 + threadIdx.x;    // < 147456
    int k = idx / 384, n = idx % 384;
    g_c3h[((size_t)(k >> 1) * 384 + n) * 2 + (k & 1)] = __float2half_rn(c3[idx]);
}

// ---------------- mid0 fp16 mma: t2 = t1h x c2h, fused t2 reindex ------------
// M=192 (BM64), N=12288 (BN256), K=192 (BK64); 256 thr, 8 warps 2x4, warp 32x64.
static constexpr int M0_A_ROW = 144;
static constexpr int M0_A_STG = 64 * M0_A_ROW;        // 9216
static constexpr int M0_B_REG = 1056;
static constexpr int M0_B_STG = 32 * M0_B_REG;        // 33792
static constexpr int M0_STG   = M0_A_STG + M0_B_STG;  // 43008
static constexpr int M0_SMEM  = 3 * M0_STG;           // 129024

__global__ __launch_bounds__(256, 1)
void gemm_mid0h() {
    extern __shared__ char smem[];
    uint32_t sb = smem_u32(smem);
    int tid  = threadIdx.x;
    int warp = tid >> 5, lane = tid & 31;
    int wm = warp >> 2, wn = warp & 3;          // 2 x 4 warp grid
    int g  = lane >> 2, tg = lane & 3;
    int col0 = blockIdx.x * 256;
    int row0 = blockIdx.y * 64;

    float c[2][8][4] = {};

    // A: 512 chunks/tile: row = tid>>2, chunk-pair = tid&3 (2 chunks)
    int aRow = tid >> 2, aCp = tid & 3;
    const __half* aSrc = g_t1h + (size_t)(row0 + aRow) * 192 + aCp * 16;
    uint32_t aD0 = (uint32_t)(aRow * M0_A_ROW + aCp * 32);
    // B: 2048 chunks/tile: thread does 8
    const __half* bSrc = g_c2h + (size_t)col0 * 2;

    uint32_t aLane = (uint32_t)((wm * 32 + (lane & 15)) * M0_A_ROW + (lane >> 4) * 16);

#pragma unroll
    for (int t = 0; t < 2; ++t) {
        uint32_t base = sb + t * M0_STG;
        CP16(base + aD0,      aSrc + t * 64);
        CP16(base + aD0 + 16, aSrc + t * 64 + 8);
#pragma unroll
        for (int i = 0; i < 8; ++i) {
            int q = tid + i * 256, r = q >> 6, n4 = (q & 63) * 4;
            CP16(base + M0_A_STG + (uint32_t)(r * M0_B_REG + n4 * 4),
                 bSrc + ((size_t)(t * 32 + r) * 12288 + n4) * 2);
        }
        CP_COMMIT();
    }

    int s = 0;
    for (int t = 0; t < 3; ++t) {
        CP_WAIT1();
        __syncthreads();
        if (t + 2 < 3) {
            int tn = t + 2;
            int sn = s + 2; if (sn >= 3) sn -= 3;
            uint32_t base = sb + sn * M0_STG;
            CP16(base + aD0,      aSrc + tn * 64);
            CP16(base + aD0 + 16, aSrc + tn * 64 + 8);
#pragma unroll
            for (int i = 0; i < 8; ++i) {
                int q = tid + i * 256, r = q >> 6, n4 = (q & 63) * 4;
                CP16(base + M0_A_STG + (uint32_t)(r * M0_B_REG + n4 * 4),
                     bSrc + ((size_t)(tn * 32 + r) * 12288 + n4) * 2);
            }
        }
        CP_COMMIT();

        uint32_t abase = sb + s * M0_STG + aLane;
        const char* B = smem + s * M0_STG + M0_A_STG;

        uint32_t af[2][2][4], bf[2][8][2];
#pragma unroll
        for (int mf = 0; mf < 2; ++mf)
            ldsm_x4(af[0][mf], abase + mf * (16 * M0_A_ROW));
#pragma unroll
        for (int nf = 0; nf < 8; ++nf) {
            int n = wn * 64 + nf * 8 + g;
            bf[0][nf][0] = *(const uint32_t*)(B + tg * M0_B_REG + n * 4);
            bf[0][nf][1] = *(const uint32_t*)(B + (4 + tg) * M0_B_REG + n * 4);
        }
#pragma unroll
        for (int kg = 0; kg < 4; ++kg) {
            int cur = kg & 1, nxt = cur ^ 1;
            if (kg < 3) {
#pragma unroll
                for (int mf = 0; mf < 2; ++mf)
                    ldsm_x4(af[nxt][mf], abase + mf * (16 * M0_A_ROW) + (kg + 1) * 32);
#pragma unroll
                for (int nf = 0; nf < 8; ++nf) {
                    int n = wn * 64 + nf * 8 + g;
                    const char* br = B + (kg + 1) * 8 * M0_B_REG;
                    bf[nxt][nf][0] = *(const uint32_t*)(br + tg * M0_B_REG + n * 4);
                    bf[nxt][nf][1] = *(const uint32_t*)(br + (4 + tg) * M0_B_REG + n * 4);
                }
            }
#pragma unroll
            for (int mf = 0; mf < 2; ++mf)
#pragma unroll
                for (int nf = 0; nf < 8; ++nf)
                    mma_f16(c[mf][nf], af[cur][mf], bf[cur][nf]);
        }
        ++s; if (s == 3) s = 0;
    }

    // fused t2 reindex store: (p, e) -> g_t2h[((Ii*4+i)*128+Oo*8+o)*384+q]
#pragma unroll
    for (int nf = 0; nf < 8; ++nf) {
#pragma unroll
        for (int e2 = 0; e2 < 2; ++e2) {
            int cc = col0 + wn * 64 + nf * 8 + tg * 2 + e2;
            int io = cc / 384, q = cc - io * 384;
            int i = io >> 3, o = io & 7;
#pragma unroll
            for (int mf = 0; mf < 2; ++mf) {
#pragma unroll
                for (int r2 = 0; r2 < 2; ++r2) {
                    int p = row0 + wm * 32 + mf * 16 + g + r2 * 8;
                    int Ii = p >> 4, Oo = p & 15;
                    g_t2h[((size_t)((Ii * 4 + i) * 128 + Oo * 8 + o)) * 384 + q]
                        = __float2half_rn(c[mf][nf][r2 * 2 + e2]);
                }
            }
        }
    }
}

// ---------------- mid1 GEMM fp16 mma: t3 = t2h x c3h, fused t3 layout -------
static constexpr int M1_A_ROW = 144;
static constexpr int M1_A_STG = 128 * M1_A_ROW;
static constexpr int M1_B_REG = 528;
static constexpr int M1_B_STG = 32 * M1_B_REG;
static constexpr int M1_STG   = M1_A_STG + M1_B_STG;
static constexpr int M1_SMEM  = 3 * M1_STG;

__global__ __launch_bounds__(256, 1)
void k_mid1h() {
    extern __shared__ char smem[];
    uint32_t sb = smem_u32(smem);
    int tid  = threadIdx.x;
    int warp = tid >> 5, lane = tid & 31;
    int wm = warp >> 2, wn = warp & 3;
    int g  = lane >> 2, tg = lane & 3;
    int bn = blockIdx.x * 128;
    int row0 = blockIdx.y * 128;

    float c[4][4][4] = {};

    int aRow = tid >> 1, aHalf = tid & 1;
    const __half* aSrc = g_t2h + (size_t)(row0 + aRow) * 384 + aHalf * 32;
    uint32_t aD0 = (uint32_t)(aRow * M1_A_ROW + aHalf * 64);
    const __half* bSrc = g_c3h + (size_t)bn * 2;

    uint32_t aLane = (uint32_t)((wm * 64 + (lane & 15)) * M1_A_ROW + (lane >> 4) * 16);

#pragma unroll
    for (int t = 0; t < 2; ++t) {
        uint32_t base = sb + t * M1_STG;
#pragma unroll
        for (int j = 0; j < 4; ++j)
            CP16(base + aD0 + j * 16, aSrc + t * 64 + j * 8);
#pragma unroll
        for (int i = 0; i < 4; ++i) {
            int q = tid + i * 256, r = q >> 5, n4 = (q & 31) * 4;
            CP16(base + M1_A_STG + (uint32_t)(r * M1_B_REG + n4 * 4),
                 bSrc + ((size_t)(t * 32 + r) * 384 + n4) * 2);
        }
        CP_COMMIT();
    }

    int s = 0;
    for (int t = 0; t < 6; ++t) {
        CP_WAIT1();
        __syncthreads();
        if (t + 2 < 6) {
            int tn = t + 2;
            int sn = s + 2; if (sn >= 3) sn -= 3;
            uint32_t base = sb + sn * M1_STG;
#pragma unroll
            for (int j = 0; j < 4; ++j)
                CP16(base + aD0 + j * 16, aSrc + tn * 64 + j * 8);
#pragma unroll
            for (int i = 0; i < 4; ++i) {
                int q = tid + i * 256, r = q >> 5, n4 = (q & 31) * 4;
                CP16(base + M1_A_STG + (uint32_t)(r * M1_B_REG + n4 * 4),
                     bSrc + ((size_t)(tn * 32 + r) * 384 + n4) * 2);
            }
        }
        CP_COMMIT();

        uint32_t abase = sb + s * M1_STG + aLane;
        const char* B = smem + s * M1_STG + M1_A_STG;

        uint32_t af[2][4][4], bf[2][4][2];
#pragma unroll
        for (int mf = 0; mf < 4; ++mf)
            ldsm_x4(af[0][mf], abase + mf * (16 * M1_A_ROW));
#pragma unroll
        for (int nf = 0; nf < 4; ++nf) {
            int n = wn * 32 + nf * 8 + g;
            bf[0][nf][0] = *(const uint32_t*)(B + tg * M1_B_REG + n * 4);
            bf[0][nf][1] = *(const uint32_t*)(B + (4 + tg) * M1_B_REG + n * 4);
        }
#pragma unroll
        for (int kg = 0; kg < 4; ++kg) {
            int cur = kg & 1, nxt = cur ^ 1;
            if (kg < 3) {
#pragma unroll
                for (int mf = 0; mf < 4; ++mf)
                    ldsm_x4(af[nxt][mf], abase + mf * (16 * M1_A_ROW) + (kg + 1) * 32);
#pragma unroll
                for (int nf = 0; nf < 4; ++nf) {
                    int n = wn * 32 + nf * 8 + g;
                    const char* br = B + (kg + 1) * 8 * M1_B_REG;
                    bf[nxt][nf][0] = *(const uint32_t*)(br + tg * M1_B_REG + n * 4);
                    bf[nxt][nf][1] = *(const uint32_t*)(br + (4 + tg) * M1_B_REG + n * 4);
                }
            }
#pragma unroll
            for (int mf = 0; mf < 4; ++mf)
#pragma unroll
                for (int nf = 0; nf < 4; ++nf)
                    mma_f16(c[mf][nf], af[cur][mf], bf[cur][nf]);
        }
        ++s; if (s == 3) s = 0;
    }

#pragma unroll
    for (int nf = 0; nf < 4; ++nf) {
#pragma unroll
        for (int e2 = 0; e2 < 2; ++e2) {
            int e = bn + wn * 32 + nf * 8 + tg * 2 + e2;
            int gg = e >> 4, q = e & 15;
            int i3 = gg / 6, o3 = gg - 6 * i3;
#pragma unroll
            for (int mf = 0; mf < 4; ++mf) {
#pragma unroll
                for (int r2 = 0; r2 < 2; ++r2) {
                    int r = row0 + wm * 64 + mf * 16 + g + r2 * 8;
                    int Ii2 = r >> 7, Oo2 = r & 127;
                    g_t3[((size_t)((Ii2 * 4 + i3) * 768 + Oo2 * 6 + o3)) * 16 + q]
                        = c[mf][nf][r2 * 2 + e2];
                }
            }
        }
    }
}

// step 4: build M as fp16 pairs g_Mh[(kp*3072 + n)*2 + (k&1)]
__global__ void k_t4(const float* __restrict__ c4) {
    __shared__ float Bs[256];
    int tid = threadIdx.x;
    Bs[tid] = c4[tid];
    __syncthreads();
    int p = blockIdx.x * 256 + tid;
    float a[16];
#pragma unroll
    for (int j = 0; j < 4; ++j) {
        float4 v = *(const float4*)&g_t3[(size_t)p * 16 + j * 4];
        a[j * 4 + 0] = v.x; a[j * 4 + 1] = v.y; a[j * 4 + 2] = v.z; a[j * 4 + 3] = v.w;
    }
    int Ii3 = p / 768, Oo3 = p % 768;
#pragma unroll
    for (int nn = 0; nn < 16; ++nn) {
        float acc = 0.f;
#pragma unroll
        for (int q = 0; q < 16; ++q) acc += a[q] * Bs[q * 16 + nn];
        int i4 = nn >> 2, o4 = nn & 3;
        int k = Ii3 * 4 + i4, n = Oo3 * 4 + o4;
        g_Mh[((size_t)(k >> 1) * 3072 + n) * 2 + (k & 1)] = __float2half_rn(acc);
    }
}

// ---------------- main GEMM (R10 exact): Y = X * M + bias -------------------
// BM=128, BN=256, BK=64; 256 threads, 8 warps (2x4), warp tile 64x64.
static constexpr int A_ROW_B  = 144;
static constexpr int A_STAGE  = 128 * A_ROW_B;        // 18432
static constexpr int B_REG_B  = 1056;
static constexpr int B_STAGE  = 32 * B_REG_B;         // 33792
static constexpr int STAGE    = A_STAGE + B_STAGE;    // 52224
static constexpr int SMEM_MAIN = 3 * STAGE;           // 156672

__global__ __launch_bounds__(256, 1)
void k_main(const float* __restrict__ bias, float* __restrict__ Y) {
    extern __shared__ char smem[];
    uint32_t sb = smem_u32(smem);

    int tid  = threadIdx.x;
    int warp = tid >> 5, lane = tid & 31;
    int wm = warp >> 2, wn = warp & 3;
    int g  = lane >> 2, tg = lane & 3;

    int col0 = blockIdx.x * 256;
    int row0 = blockIdx.y * 128;

    float c[4][8][4] = {};

    int aRow = tid >> 1, aHalf = tid & 1;
    const __half* aSrc = g_Xh + (size_t)(row0 + aRow) * 768 + aHalf * 32;
    uint32_t aD0 = (uint32_t)(aRow * A_ROW_B + aHalf * 64);
    const __half* bSrc = g_Mh + (size_t)col0 * 2;

    uint32_t aLane = (uint32_t)((wm * 64 + (lane & 15)) * A_ROW_B + (lane >> 4) * 16);

#pragma unroll
    for (int t = 0; t < 2; ++t) {
        uint32_t base = sb + t * STAGE;
#pragma unroll
        for (int j = 0; j < 4; ++j)
            CP16(base + aD0 + j * 16, aSrc + t * 64 + j * 8);
#pragma unroll
        for (int i = 0; i < 8; ++i) {
            int q = tid + i * 256, r = q >> 6, n4 = (q & 63) * 4;
            CP16(base + A_STAGE + (uint32_t)(r * B_REG_B + n4 * 4),
                 bSrc + ((size_t)(t * 32 + r) * 3072 + n4) * 2);
        }
        CP_COMMIT();
    }

    int s = 0;
    for (int t = 0; t < 12; ++t) {
        CP_WAIT1();
        __syncthreads();

        if (t + 2 < 12) {
            int tn = t + 2;
            int sn = s + 2; if (sn >= 3) sn -= 3;
            uint32_t base = sb + sn * STAGE;
#pragma unroll
            for (int j = 0; j < 4; ++j)
                CP16(base + aD0 + j * 16, aSrc + tn * 64 + j * 8);
#pragma unroll
            for (int i = 0; i < 8; ++i) {
                int q = tid + i * 256, r = q >> 6, n4 = (q & 63) * 4;
                CP16(base + A_STAGE + (uint32_t)(r * B_REG_B + n4 * 4),
                     bSrc + ((size_t)(tn * 32 + r) * 3072 + n4) * 2);
            }
        }
        CP_COMMIT();

        uint32_t abase = sb + s * STAGE + aLane;
        const char* B = smem + s * STAGE + A_STAGE;

        uint32_t af[2][4][4], bf[2][8][2];
#pragma unroll
        for (int mf = 0; mf < 4; ++mf)
            ldsm_x4(af[0][mf], abase + mf * (16 * A_ROW_B));
#pragma unroll
        for (int nf = 0; nf < 8; ++nf) {
            int n = wn * 64 + nf * 8 + g;
            bf[0][nf][0] = *(const uint32_t*)(B + tg * B_REG_B + n * 4);
            bf[0][nf][1] = *(const uint32_t*)(B + (4 + tg) * B_REG_B + n * 4);
        }

#pragma unroll
        for (int kg = 0; kg < 4; ++kg) {
            int cur = kg & 1, nxt = cur ^ 1;
            if (kg < 3) {
#pragma unroll
                for (int mf = 0; mf < 4; ++mf)
                    ldsm_x4(af[nxt][mf], abase + mf * (16 * A_ROW_B) + (kg + 1) * 32);
#pragma unroll
                for (int nf = 0; nf < 8; ++nf) {
                    int n = wn * 64 + nf * 8 + g;
                    const char* br = B + (kg + 1) * 8 * B_REG_B;
                    bf[nxt][nf][0] = *(const uint32_t*)(br + tg * B_REG_B + n * 4);
                    bf[nxt][nf][1] = *(const uint32_t*)(br + (4 + tg) * B_REG_B + n * 4);
                }
            }
#pragma unroll
            for (int mf = 0; mf < 4; ++mf)
#pragma unroll
                for (int nf = 0; nf < 8; ++nf)
                    mma_f16(c[mf][nf], af[cur][mf], bf[cur][nf]);
        }
        ++s; if (s == 3) s = 0;
    }

    // epilogue: add bias, store
#pragma unroll
    for (int nf = 0; nf < 8; ++nf) {
        int cc = col0 + wn * 64 + nf * 8 + tg * 2;
        float b0 = bias[cc], b1 = bias[cc + 1];
#pragma unroll
        for (int mf = 0; mf < 4; ++mf) {
            int r = row0 + wm * 64 + mf * 16 + g;
            float2 v0 = make_float2(c[mf][nf][0] + b0, c[mf][nf][1] + b1);
            float2 v1 = make_float2(c[mf][nf][2] + b0, c[mf][nf][3] + b1);
            *(float2*)&Y[(size_t)r * 3072 + cc]       = v0;
            *(float2*)&Y[(size_t)(r + 8) * 3072 + cc] = v1;
        }
    }
}

// ---------------- launch -----------------------------------------------------
extern "C" void kernel_launch(void* const* d_in, const int* in_sizes, int n_in,
                              void* d_out, int out_size) {
    const float* x    = (const float*)d_in[0];
    const float* c0   = (const float*)d_in[1];
    const float* c1   = (const float*)d_in[2];
    const float* c2   = (const float*)d_in[3];
    const float* c3   = (const float*)d_in[4];
    const float* c4   = (const float*)d_in[5];
    const float* bias = (const float*)d_in[6];
    float* y = (float*)d_out;

    k_pre<<<(32768UL * 768 / 4) / 256, 256>>>(x);
    k_t1<<<144, 256>>>(c0, c1);
    k_c2h<<<(192 * 12288) / 256, 256>>>(c2);
    k_c3h<<<147456 / 256, 256>>>(c3);

    cudaFuncSetAttribute(gemm_mid0h, cudaFuncAttributeMaxDynamicSharedMemorySize, M0_SMEM);
    {
        dim3 grid(12288 / 256, 192 / 64);
        gemm_mid0h<<<grid, 256, M0_SMEM>>>();
    }
    cudaFuncSetAttribute(k_mid1h, cudaFuncAttributeMaxDynamicSharedMemorySize, M1_SMEM);
    {
        dim3 grid(384 / 128, 6144 / 128);
        k_mid1h<<<grid, 256, M1_SMEM>>>();
    }
    k_t4<<<147456 / 256, 256>>>(c4);

    cudaFuncSetAttribute(k_main, cudaFuncAttributeMaxDynamicSharedMemorySize, SMEM_MAIN);
    {
        dim3 grid(3072 / 256, 32768 / 128);
        k_main<<<grid, 256, SMEM_MAIN>>>(bias, y);
    }
}